// round 2
// baseline (speedup 1.0000x reference)
#include <cuda_runtime.h>
#include <math.h>

#define HW   16384
#define Hh   128
#define Ww   128
#define Cc   256
#define Qq   256
#define Ee   192
#define Bb   4
#define Stq  4
#define NH   4
#define DH   64
#define EPSS 1e-5f

// ---------------- scratch (static device allocations; no cudaMalloc) ----------------
__device__ float g_mt[Bb * Qq * HW];        // 67 MB  mt[b][q][p]
__device__ float g_eg[Bb * Ee * HW];        // 50 MB  evidence*gate [b][e][p]
__device__ float g_att[Stq * Bb * NH * HW]; // 4 MB   scores -> attw, row=((t*4+b)*4+n)
__device__ float g_qk[Stq * NH * Qq];       // qk[t][n][c] (prescaled by 1/8)
__device__ float g_sb[Stq * NH];            // q . bk (prescaled by 1/8)
__device__ float g_pooled[Stq * Bb * NH * Qq];
__device__ float g_gamma[Stq * Bb * Ee];
__device__ float g_beta[Stq * Bb * Ee];
__device__ unsigned char g_mask[Bb * Stq];  // canonical uint8 mask [b][t]

// ---------------- Kmask: sniff active_mask dtype, normalize to uint8 ----------------
__global__ void k_mask(const unsigned char* __restrict__ raw) {
    if (threadIdx.x != 0) return;
    unsigned char b[16];
    bool bytish = true;
    #pragma unroll
    for (int i = 0; i < 16; ++i) { b[i] = raw[i]; if (b[i] > 1) bytish = false; }
    if (!bytish) {
        // float32 storage (bytes of 1.0f contain 0x80/0x3F)
        const float* f = (const float*)raw;
        for (int i = 0; i < 16; ++i) g_mask[i] = (f[i] != 0.0f) ? 1 : 0;
    } else {
        bool int32pat = true;
        for (int i = 0; i < 16; ++i)
            if ((i & 3) != 0 && b[i] != 0) int32pat = false;
        if (int32pat) {
            const int* d = (const int*)raw;
            for (int i = 0; i < 16; ++i) g_mask[i] = (d[i] != 0) ? 1 : 0;
        } else {
            for (int i = 0; i < 16; ++i) g_mask[i] = b[i];
        }
    }
}

// ---------------- K0: q = stem@Wq^T+bq ; qk = q^T Wk ; zero pooled ----------------
__global__ void k0_qk(const float* __restrict__ stem,
                      const float* __restrict__ ipw,
                      const float* __restrict__ ipb) {
    __shared__ float q_s[Stq * Qq];
    const int tid = threadIdx.x;
    for (int o = tid; o < Stq * Qq; o += 256) {
        const int t = o >> 8, nd = o & 255;
        float s = ipb[nd];
        const float* wr = ipw + nd * Qq;
        const float* xr = stem + t * Qq;
        #pragma unroll 4
        for (int j = 0; j < Qq; ++j) s = fmaf(xr[j], wr[j], s);
        q_s[o] = s;
    }
    __syncthreads();
    for (int o = tid; o < Stq * NH * Qq; o += 256) {
        const int c = o & 255, r = o >> 8, t = r >> 2, n = r & 3;
        float s = 0.f;
        #pragma unroll 4
        for (int d = 0; d < DH; ++d)
            s = fmaf(q_s[t * 256 + n * 64 + d], ipw[(Qq + n * 64 + d) * Qq + c], s);
        g_qk[o] = 0.125f * s;
    }
    if (tid < Stq * NH) {
        const int t = tid >> 2, n = tid & 3;
        float s = 0.f;
        for (int d = 0; d < DH; ++d)
            s = fmaf(q_s[t * 256 + n * 64 + d], ipb[Qq + n * 64 + d], s);
        g_sb[tid] = 0.125f * s;
    }
    for (int o = tid; o < Stq * Bb * NH * Qq; o += 256) g_pooled[o] = 0.f;
}

// ---------------- K1: mt[b][q][p] = sum_c mem[b][c][p] * Wm[q][c] ----------------
__global__ void __launch_bounds__(256) k1_mt(const float* __restrict__ mem,
                                             const float* __restrict__ mpw) {
    __shared__ float A_s[16][64];
    __shared__ float B_s[16][128];
    const int b = blockIdx.z, q0 = blockIdx.y * 64, p0 = blockIdx.x * 128;
    const int tid = threadIdx.x, ty = tid >> 5, tx = tid & 31;
    float acc[8][4] = {};
    const float* memB = mem + b * Cc * HW;
    for (int c0 = 0; c0 < Cc; c0 += 16) {
        for (int i = tid; i < 1024; i += 256) {
            const int qq = i >> 4, cc = i & 15;
            A_s[cc][qq] = mpw[(q0 + qq) * Cc + c0 + cc];
        }
        for (int i = tid; i < 2048; i += 256) {
            const int cc = i >> 7, pp = i & 127;
            B_s[cc][pp] = memB[(c0 + cc) * HW + p0 + pp];
        }
        __syncthreads();
        #pragma unroll
        for (int cc = 0; cc < 16; ++cc) {
            float4 a0 = *(const float4*)&A_s[cc][ty * 8];
            float4 a1 = *(const float4*)&A_s[cc][ty * 8 + 4];
            float4 bv = *(const float4*)&B_s[cc][tx * 4];
            const float a[8] = {a0.x, a0.y, a0.z, a0.w, a1.x, a1.y, a1.z, a1.w};
            const float bb[4] = {bv.x, bv.y, bv.z, bv.w};
            #pragma unroll
            for (int i = 0; i < 8; ++i)
                #pragma unroll
                for (int j = 0; j < 4; ++j) acc[i][j] = fmaf(a[i], bb[j], acc[i][j]);
        }
        __syncthreads();
    }
    float* outB = g_mt + b * Qq * HW;
    #pragma unroll
    for (int i = 0; i < 8; ++i) {
        float4 v = make_float4(acc[i][0], acc[i][1], acc[i][2], acc[i][3]);
        *(float4*)&outB[(q0 + ty * 8 + i) * HW + p0 + tx * 4] = v;
    }
}

// ---------------- K2: eg = silu(bn1(mem . ev_w)) * sigmoid(mt . gate_w + gb) ----------------
__global__ void __launch_bounds__(256) k2_eg(const float* __restrict__ mem,
                                             const float* __restrict__ evw,
                                             const float* __restrict__ gw,
                                             const float* __restrict__ gbias,
                                             const float* __restrict__ bn1g,
                                             const float* __restrict__ bn1b,
                                             const float* __restrict__ bn1m,
                                             const float* __restrict__ bn1v) {
    __shared__ float A_s[16][64];
    __shared__ float B_s[16][128];
    const int b = blockIdx.z, e0 = blockIdx.y * 64, p0 = blockIdx.x * 128;
    const int tid = threadIdx.x, ty = tid >> 5, tx = tid & 31;
    float acc1[8][4] = {}, acc2[8][4] = {};
    const float* memB = mem + b * Cc * HW;
    const float* mtB = g_mt + b * Qq * HW;

    for (int c0 = 0; c0 < Cc; c0 += 16) {
        for (int i = tid; i < 1024; i += 256) {
            const int ee = i >> 4, cc = i & 15;
            A_s[cc][ee] = evw[(e0 + ee) * Cc + c0 + cc];
        }
        for (int i = tid; i < 2048; i += 256) {
            const int cc = i >> 7, pp = i & 127;
            B_s[cc][pp] = memB[(c0 + cc) * HW + p0 + pp];
        }
        __syncthreads();
        #pragma unroll
        for (int cc = 0; cc < 16; ++cc) {
            float4 a0 = *(const float4*)&A_s[cc][ty * 8];
            float4 a1 = *(const float4*)&A_s[cc][ty * 8 + 4];
            float4 bv = *(const float4*)&B_s[cc][tx * 4];
            const float a[8] = {a0.x, a0.y, a0.z, a0.w, a1.x, a1.y, a1.z, a1.w};
            const float bb[4] = {bv.x, bv.y, bv.z, bv.w};
            #pragma unroll
            for (int i = 0; i < 8; ++i)
                #pragma unroll
                for (int j = 0; j < 4; ++j) acc1[i][j] = fmaf(a[i], bb[j], acc1[i][j]);
        }
        __syncthreads();
    }
    for (int c0 = 0; c0 < Qq; c0 += 16) {
        for (int i = tid; i < 1024; i += 256) {
            const int ee = i >> 4, cc = i & 15;
            A_s[cc][ee] = gw[(e0 + ee) * Qq + c0 + cc];
        }
        for (int i = tid; i < 2048; i += 256) {
            const int cc = i >> 7, pp = i & 127;
            B_s[cc][pp] = mtB[(c0 + cc) * HW + p0 + pp];
        }
        __syncthreads();
        #pragma unroll
        for (int cc = 0; cc < 16; ++cc) {
            float4 a0 = *(const float4*)&A_s[cc][ty * 8];
            float4 a1 = *(const float4*)&A_s[cc][ty * 8 + 4];
            float4 bv = *(const float4*)&B_s[cc][tx * 4];
            const float a[8] = {a0.x, a0.y, a0.z, a0.w, a1.x, a1.y, a1.z, a1.w};
            const float bb[4] = {bv.x, bv.y, bv.z, bv.w};
            #pragma unroll
            for (int i = 0; i < 8; ++i)
                #pragma unroll
                for (int j = 0; j < 4; ++j) acc2[i][j] = fmaf(a[i], bb[j], acc2[i][j]);
        }
        __syncthreads();
    }
    #pragma unroll
    for (int i = 0; i < 8; ++i) {
        const int e = e0 + ty * 8 + i;
        const float sc = bn1g[e] * rsqrtf(bn1v[e] + EPSS);
        const float sh = bn1b[e] - bn1m[e] * sc;
        const float gbv = gbias[e];
        float res[4];
        #pragma unroll
        for (int j = 0; j < 4; ++j) {
            const float evv = acc1[i][j] * sc + sh;
            const float ev = evv / (1.f + expf(-evv));       // silu
            const float gt = 1.f / (1.f + expf(-(acc2[i][j] + gbv)));
            res[j] = ev * gt;
        }
        *(float4*)&g_eg[(b * Ee + e) * HW + p0 + tx * 4] =
            make_float4(res[0], res[1], res[2], res[3]);
    }
}

// ---------------- K3: scores[t,b,n,p] = qk[t,n,:] . mt[b,:,p] + sb ----------------
__global__ void __launch_bounds__(256) k3_scores() {
    __shared__ float qk_s[16][256];
    __shared__ float sb_s[16];
    const int b = blockIdx.y;
    const int tid = threadIdx.x;
    const int p = blockIdx.x * 256 + tid;
    for (int i = tid; i < 4096; i += 256) qk_s[i >> 8][i & 255] = g_qk[i];
    if (tid < 16) sb_s[tid] = g_sb[tid];
    __syncthreads();
    float acc[16];
    #pragma unroll
    for (int r = 0; r < 16; ++r) acc[r] = sb_s[r];
    const float* mtB = g_mt + b * Qq * HW + p;
    #pragma unroll 4
    for (int c = 0; c < 256; ++c) {
        const float mv = mtB[c * HW];
        #pragma unroll
        for (int r = 0; r < 16; ++r) acc[r] = fmaf(qk_s[r][c], mv, acc[r]);
    }
    #pragma unroll
    for (int r = 0; r < 16; ++r) {
        const int t = r >> 2, n = r & 3;
        g_att[(t * 16 + b * 4 + n) * HW + p] = acc[r];
    }
}

// ---------------- K4: softmax over p (64 rows) ----------------
__global__ void k4_softmax() {
    const int tid = threadIdx.x;
    float* row = g_att + blockIdx.x * HW;
    __shared__ float red[256];
    float mx = -1e30f;
    for (int i = tid; i < HW; i += 256) mx = fmaxf(mx, row[i]);
    red[tid] = mx;
    __syncthreads();
    for (int s = 128; s; s >>= 1) {
        if (tid < s) red[tid] = fmaxf(red[tid], red[tid + s]);
        __syncthreads();
    }
    mx = red[0];
    __syncthreads();
    float sm = 0.f;
    for (int i = tid; i < HW; i += 256) sm += expf(row[i] - mx);
    red[tid] = sm;
    __syncthreads();
    for (int s = 128; s; s >>= 1) {
        if (tid < s) red[tid] += red[tid + s];
        __syncthreads();
    }
    const float inv = 1.f / red[0];
    for (int i = tid; i < HW; i += 256) row[i] = expf(row[i] - mx) * inv;
}

// ---------------- K5: pooled[t,b,n,c] = sum_p attw * mt[b,c,p] ----------------
__global__ void __launch_bounds__(256) k5_pooled() {
    __shared__ float mtT[64][65];
    __shared__ float awT[16][65];
    const int b = blockIdx.z, c0 = blockIdx.y * 64, slab = blockIdx.x * 1024;
    const int tid = threadIdx.x, cl = tid & 63, g = tid >> 6;
    float acc[4] = {};
    for (int pc = 0; pc < 1024; pc += 64) {
        const int pbase = slab + pc;
        for (int i = tid; i < 4096; i += 256) {
            const int cc = i >> 6, pj = i & 63;
            mtT[cc][pj] = g_mt[(b * Qq + c0 + cc) * HW + pbase + pj];
        }
        for (int i = tid; i < 1024; i += 256) {
            const int r = i >> 6, pj = i & 63;
            const int t = r >> 2, n = r & 3;
            awT[r][pj] = g_att[(t * 16 + b * 4 + n) * HW + pbase + pj];
        }
        __syncthreads();
        #pragma unroll 16
        for (int pj = 0; pj < 64; ++pj) {
            const float mv = mtT[cl][pj];
            #pragma unroll
            for (int rr = 0; rr < 4; ++rr)
                acc[rr] = fmaf(awT[g * 4 + rr][pj], mv, acc[rr]);
        }
        __syncthreads();
    }
    #pragma unroll
    for (int rr = 0; rr < 4; ++rr) {
        const int r = g * 4 + rr, t = r >> 2, n = r & 3;
        atomicAdd(&g_pooled[((t * 4 + b) * 4 + n) * Qq + c0 + cl], acc[rr]);
    }
}

// ---------------- K6: attended -> state -> gamma/beta (tiny) ----------------
__global__ void k6_state(const float* __restrict__ ipw, const float* __restrict__ ipb,
                         const float* __restrict__ opw, const float* __restrict__ opb,
                         const float* __restrict__ fw, const float* __restrict__ fb) {
    const int tb = blockIdx.x;  // t*4+b
    __shared__ float pl[1024], att[256], st[256];
    const int tid = threadIdx.x, lane = tid & 31, warp = tid >> 5;
    for (int i = tid; i < 1024; i += 256) pl[i] = g_pooled[tb * 1024 + i];
    __syncthreads();
    for (int o = warp * 32; o < warp * 32 + 32; ++o) {
        const int n = o >> 6;
        float s = 0.f;
        for (int c = lane; c < 256; c += 32) s = fmaf(pl[n * 256 + c], ipw[(512 + o) * 256 + c], s);
        #pragma unroll
        for (int off = 16; off; off >>= 1) s += __shfl_xor_sync(0xffffffffu, s, off);
        if (lane == 0) att[o] = s + ipb[512 + o];
    }
    __syncthreads();
    for (int o = warp * 32; o < warp * 32 + 32; ++o) {
        float s = 0.f;
        for (int c = lane; c < 256; c += 32) s = fmaf(att[c], opw[o * 256 + c], s);
        #pragma unroll
        for (int off = 16; off; off >>= 1) s += __shfl_xor_sync(0xffffffffu, s, off);
        if (lane == 0) st[o] = s + opb[o];
    }
    __syncthreads();
    for (int o = warp * 48; o < warp * 48 + 48; ++o) {
        float s = 0.f;
        for (int c = lane; c < 256; c += 32) s = fmaf(st[c], fw[o * 256 + c], s);
        #pragma unroll
        for (int off = 16; off; off >>= 1) s += __shfl_xor_sync(0xffffffffu, s, off);
        if (lane == 0) {
            s += fb[o];
            if (o < Ee) g_gamma[tb * Ee + o] = s;
            else        g_beta[tb * Ee + o - Ee] = s;
        }
    }
}

// ---------------- K7: 3x3 conv (x built on the fly) + bn2 + silu + mask ----------------
__global__ void __launch_bounds__(256) k7_conv(const float* __restrict__ w,
                                               const float* __restrict__ bn2g,
                                               const float* __restrict__ bn2b,
                                               const float* __restrict__ bn2m,
                                               const float* __restrict__ bn2v,
                                               float* __restrict__ out) {
    const int img = blockIdx.z / 6;            // t*4+b
    const int f0 = (blockIdx.z % 6) * 32;
    const int t = img >> 2, b = img & 3;
    const int h0 = blockIdx.y * 16, w0 = blockIdx.x * 32;
    const int tid = threadIdx.x;

    if (!g_mask[b * Stq + t]) {                // active_mask[b][t] == 0 -> zeros
        for (int i = tid; i < 32 * 16 * 32; i += 256) {
            const int f = i >> 9, rem = i & 511, r = rem >> 5, c = rem & 31;
            out[((img * Ee + f0 + f) * Hh + h0 + r) * Ww + w0 + c] = 0.f;
        }
        return;
    }

    __shared__ float in_s[8][18][35];
    __shared__ float w_s[72][32];
    const int tf = tid >> 6, tpg = tid & 63;
    const int row = tpg >> 2, col8 = (tpg & 3) << 3;
    float acc[8][8] = {};
    const float* egB = g_eg + b * Ee * HW;
    const float* gam = g_gamma + img * Ee;
    const float* bet = g_beta + img * Ee;

    for (int e0 = 0; e0 < Ee; e0 += 8) {
        for (int i = tid; i < 2304; i += 256) {
            const int f = i & 31, rest = i >> 5;         // rest = e*9+k
            const int e = rest / 9, k = rest - e * 9;
            w_s[rest][f] = w[((f0 + f) * Ee + e0 + e) * 9 + k];
        }
        for (int i = tid; i < 8 * 18 * 34; i += 256) {
            const int e = i / 612, rem = i - e * 612, rr = rem / 34, cc = rem - rr * 34;
            const int gh = h0 - 1 + rr, gw = w0 - 1 + cc;
            float v = 0.f;
            if (gh >= 0 && gh < Hh && gw >= 0 && gw < Ww) {
                v = egB[(e0 + e) * HW + gh * Ww + gw] * (1.f + gam[e0 + e]) + bet[e0 + e];
            }
            in_s[e][rr][cc] = v;
        }
        __syncthreads();
        for (int e = 0; e < 8; ++e) {
            #pragma unroll
            for (int k9 = 0; k9 < 9; ++k9) {
                const int ky = k9 / 3, kx = k9 - ky * 3;
                float wv[8], iv[8];
                #pragma unroll
                for (int i = 0; i < 8; ++i) wv[i] = w_s[e * 9 + k9][tf * 8 + i];
                const float* ip = &in_s[e][row + ky][col8 + kx];
                #pragma unroll
                for (int j = 0; j < 8; ++j) iv[j] = ip[j];
                #pragma unroll
                for (int i = 0; i < 8; ++i)
                    #pragma unroll
                    for (int j = 0; j < 8; ++j) acc[i][j] = fmaf(wv[i], iv[j], acc[i][j]);
            }
        }
        __syncthreads();
    }

    #pragma unroll
    for (int i = 0; i < 8; ++i) {
        const int f = f0 + tf * 8 + i;
        const float sc = bn2g[f] * rsqrtf(bn2v[f] + EPSS);
        const float sh = bn2b[f] - bn2m[f] * sc;
        float* orow = out + ((img * Ee + f) * Hh + h0 + row) * Ww + w0 + col8;
        #pragma unroll
        for (int j = 0; j < 8; ++j) {
            const float y = acc[i][j] * sc + sh;
            orow[j] = y / (1.f + expf(-y));   // silu; mask==1 here
        }
    }
}

// ---------------- launch ----------------
extern "C" void kernel_launch(void* const* d_in, const int* in_sizes, int n_in,
                              void* d_out, int out_size) {
    const float* memory = (const float*)d_in[0];
    const unsigned char* active_mask_raw = (const unsigned char*)d_in[1];
    const float* stem = (const float*)d_in[2];
    const float* mpw  = (const float*)d_in[3];
    const float* ipw  = (const float*)d_in[4];
    const float* ipb  = (const float*)d_in[5];
    const float* opw  = (const float*)d_in[6];
    const float* opb  = (const float*)d_in[7];
    const float* evw  = (const float*)d_in[8];
    const float* bn1g = (const float*)d_in[9];
    const float* bn1b = (const float*)d_in[10];
    const float* bn1m = (const float*)d_in[11];
    const float* bn1v = (const float*)d_in[12];
    const float* gw   = (const float*)d_in[13];
    const float* gbb  = (const float*)d_in[14];
    const float* fw   = (const float*)d_in[15];
    const float* fb   = (const float*)d_in[16];
    const float* outw = (const float*)d_in[17];
    const float* bn2g = (const float*)d_in[18];
    const float* bn2b = (const float*)d_in[19];
    const float* bn2m = (const float*)d_in[20];
    const float* bn2v = (const float*)d_in[21];
    float* out = (float*)d_out;

    k_mask<<<1, 1>>>(active_mask_raw);
    k1_mt<<<dim3(128, 4, 4), 256>>>(memory, mpw);
    k0_qk<<<1, 256>>>(stem, ipw, ipb);
    k2_eg<<<dim3(128, 3, 4), 256>>>(memory, evw, gw, gbb, bn1g, bn1b, bn1m, bn1v);
    k3_scores<<<dim3(64, 4), 256>>>();
    k4_softmax<<<64, 256>>>();
    k5_pooled<<<dim3(16, 4, 4), 256>>>();
    k6_state<<<16, 256>>>(ipw, ipb, opw, opb, fw, fb);
    k7_conv<<<dim3(4, 8, 96), 256>>>(outw, bn2g, bn2b, bn2m, bn2v, out);
}

// round 6
// speedup vs baseline: 1.1781x; 1.1781x over previous
#include <cuda_runtime.h>
#include <math.h>

#define HW   16384
#define Hh   128
#define Ww   128
#define Cc   256
#define Qq   256
#define Ee   192
#define Bb   4
#define Stq  4
#define NH   4
#define DH   64
#define EPSS 1e-5f

// ---------------- packed fp32 (Blackwell FFMA2) helpers ----------------
typedef unsigned long long f32x2;
__device__ __forceinline__ f32x2 pack2(float lo, float hi) {
    f32x2 r; asm("mov.b64 %0, {%1,%2};" : "=l"(r) : "f"(lo), "f"(hi)); return r;
}
__device__ __forceinline__ f32x2 fma2(f32x2 a, f32x2 b, f32x2 c) {
    f32x2 d; asm("fma.rn.f32x2 %0, %1, %2, %3;" : "=l"(d) : "l"(a), "l"(b), "l"(c)); return d;
}
__device__ __forceinline__ float2 unpk(f32x2 a) {
    float2 v; asm("mov.b64 {%0,%1}, %2;" : "=f"(v.x), "=f"(v.y) : "l"(a)); return v;
}

// ---------------- scratch (static device allocations; no cudaMalloc) ----------------
__device__ float g_mt[Bb * Qq * HW];        // 67 MB  mt[b][q][p]
__device__ float g_eg[Bb * Ee * HW];        // 50 MB  evidence*gate [b][e][p]
__device__ float g_att[Stq * Bb * NH * HW]; // 4 MB   scores -> attw, row=((t*4+b)*4+n)
__device__ float g_qk[Stq * NH * Qq];       // qk[t][n][c] (prescaled by 1/8)
__device__ float g_sb[Stq * NH];            // q . bk (prescaled by 1/8)
__device__ float g_pooled[Stq * Bb * NH * Qq];
__device__ float g_gamma[Stq * Bb * Ee];
__device__ float g_beta[Stq * Bb * Ee];
__device__ unsigned char g_mask[Bb * Stq];  // canonical uint8 mask [b][t]

// ---------------- Kmask: sniff active_mask dtype, normalize to uint8 ----------------
__global__ void k_mask(const unsigned char* __restrict__ raw) {
    if (threadIdx.x != 0) return;
    unsigned char b[16];
    bool bytish = true;
    #pragma unroll
    for (int i = 0; i < 16; ++i) { b[i] = raw[i]; if (b[i] > 1) bytish = false; }
    if (!bytish) {
        const float* f = (const float*)raw;
        for (int i = 0; i < 16; ++i) g_mask[i] = (f[i] != 0.0f) ? 1 : 0;
    } else {
        bool int32pat = true;
        for (int i = 0; i < 16; ++i)
            if ((i & 3) != 0 && b[i] != 0) int32pat = false;
        if (int32pat) {
            const int* d = (const int*)raw;
            for (int i = 0; i < 16; ++i) g_mask[i] = (d[i] != 0) ? 1 : 0;
        } else {
            for (int i = 0; i < 16; ++i) g_mask[i] = b[i];
        }
    }
}

// ---------------- K0: q = stem@Wq^T+bq ; qk = q^T Wk ; zero pooled ----------------
__global__ void k0_qk(const float* __restrict__ stem,
                      const float* __restrict__ ipw,
                      const float* __restrict__ ipb) {
    __shared__ float q_s[Stq * Qq];
    const int tid = threadIdx.x;
    for (int o = tid; o < Stq * Qq; o += 256) {
        const int t = o >> 8, nd = o & 255;
        float s = ipb[nd];
        const float* wr = ipw + nd * Qq;
        const float* xr = stem + t * Qq;
        #pragma unroll 4
        for (int j = 0; j < Qq; ++j) s = fmaf(xr[j], wr[j], s);
        q_s[o] = s;
    }
    __syncthreads();
    for (int o = tid; o < Stq * NH * Qq; o += 256) {
        const int c = o & 255, r = o >> 8, t = r >> 2, n = r & 3;
        float s = 0.f;
        #pragma unroll 4
        for (int d = 0; d < DH; ++d)
            s = fmaf(q_s[t * 256 + n * 64 + d], ipw[(Qq + n * 64 + d) * Qq + c], s);
        g_qk[o] = 0.125f * s;
    }
    if (tid < Stq * NH) {
        const int t = tid >> 2, n = tid & 3;
        float s = 0.f;
        for (int d = 0; d < DH; ++d)
            s = fmaf(q_s[t * 256 + n * 64 + d], ipb[Qq + n * 64 + d], s);
        g_sb[tid] = 0.125f * s;
    }
    for (int o = tid; o < Stq * Bb * NH * Qq; o += 256) g_pooled[o] = 0.f;
}

// ---------------- K1: mt[b][q][p] = sum_c mem[b][c][p] * Wm[q][c] ----------------
__global__ void __launch_bounds__(256) k1_mt(const float* __restrict__ mem,
                                             const float* __restrict__ mpw) {
    __shared__ float A_s[16][64];
    __shared__ float B_s[16][128];
    const int b = blockIdx.z, q0 = blockIdx.y * 64, p0 = blockIdx.x * 128;
    const int tid = threadIdx.x, ty = tid >> 5, tx = tid & 31;
    f32x2 acc[8][2];
    #pragma unroll
    for (int i = 0; i < 8; ++i) { acc[i][0] = 0ull; acc[i][1] = 0ull; }
    const float* memB = mem + b * Cc * HW;
    for (int c0 = 0; c0 < Cc; c0 += 16) {
        for (int i = tid; i < 1024; i += 256) {
            const int qq = i >> 4, cc = i & 15;
            A_s[cc][qq] = mpw[(q0 + qq) * Cc + c0 + cc];
        }
        for (int i = tid; i < 2048; i += 256) {
            const int cc = i >> 7, pp = i & 127;
            B_s[cc][pp] = memB[(c0 + cc) * HW + p0 + pp];
        }
        __syncthreads();
        #pragma unroll
        for (int cc = 0; cc < 16; ++cc) {
            float4 a0 = *(const float4*)&A_s[cc][ty * 8];
            float4 a1 = *(const float4*)&A_s[cc][ty * 8 + 4];
            float4 bv = *(const float4*)&B_s[cc][tx * 4];
            const f32x2 b0 = pack2(bv.x, bv.y), b1 = pack2(bv.z, bv.w);
            const float a[8] = {a0.x, a0.y, a0.z, a0.w, a1.x, a1.y, a1.z, a1.w};
            #pragma unroll
            for (int i = 0; i < 8; ++i) {
                const f32x2 ab = pack2(a[i], a[i]);
                acc[i][0] = fma2(ab, b0, acc[i][0]);
                acc[i][1] = fma2(ab, b1, acc[i][1]);
            }
        }
        __syncthreads();
    }
    float* outB = g_mt + b * Qq * HW;
    #pragma unroll
    for (int i = 0; i < 8; ++i) {
        const float2 u0 = unpk(acc[i][0]), u1 = unpk(acc[i][1]);
        *(float4*)&outB[(q0 + ty * 8 + i) * HW + p0 + tx * 4] =
            make_float4(u0.x, u0.y, u1.x, u1.y);
    }
}

// ---------------- K2: eg = silu(bn1(mem . ev_w)) * sigmoid(mt . gate_w + gb) ----------------
__global__ void __launch_bounds__(256) k2_eg(const float* __restrict__ mem,
                                             const float* __restrict__ evw,
                                             const float* __restrict__ gw,
                                             const float* __restrict__ gbias,
                                             const float* __restrict__ bn1g,
                                             const float* __restrict__ bn1b,
                                             const float* __restrict__ bn1m,
                                             const float* __restrict__ bn1v) {
    __shared__ float A_s[16][64];
    __shared__ float B_s[16][128];
    const int b = blockIdx.z, e0 = blockIdx.y * 64, p0 = blockIdx.x * 128;
    const int tid = threadIdx.x, ty = tid >> 5, tx = tid & 31;
    f32x2 acc1[8][2], acc2[8][2];
    #pragma unroll
    for (int i = 0; i < 8; ++i) {
        acc1[i][0] = acc1[i][1] = 0ull;
        acc2[i][0] = acc2[i][1] = 0ull;
    }
    const float* memB = mem + b * Cc * HW;
    const float* mtB = g_mt + b * Qq * HW;

    for (int c0 = 0; c0 < Cc; c0 += 16) {
        for (int i = tid; i < 1024; i += 256) {
            const int ee = i >> 4, cc = i & 15;
            A_s[cc][ee] = evw[(e0 + ee) * Cc + c0 + cc];
        }
        for (int i = tid; i < 2048; i += 256) {
            const int cc = i >> 7, pp = i & 127;
            B_s[cc][pp] = memB[(c0 + cc) * HW + p0 + pp];
        }
        __syncthreads();
        #pragma unroll
        for (int cc = 0; cc < 16; ++cc) {
            float4 a0 = *(const float4*)&A_s[cc][ty * 8];
            float4 a1 = *(const float4*)&A_s[cc][ty * 8 + 4];
            float4 bv = *(const float4*)&B_s[cc][tx * 4];
            const f32x2 b0 = pack2(bv.x, bv.y), b1 = pack2(bv.z, bv.w);
            const float a[8] = {a0.x, a0.y, a0.z, a0.w, a1.x, a1.y, a1.z, a1.w};
            #pragma unroll
            for (int i = 0; i < 8; ++i) {
                const f32x2 ab = pack2(a[i], a[i]);
                acc1[i][0] = fma2(ab, b0, acc1[i][0]);
                acc1[i][1] = fma2(ab, b1, acc1[i][1]);
            }
        }
        __syncthreads();
    }
    for (int c0 = 0; c0 < Qq; c0 += 16) {
        for (int i = tid; i < 1024; i += 256) {
            const int ee = i >> 4, cc = i & 15;
            A_s[cc][ee] = gw[(e0 + ee) * Qq + c0 + cc];
        }
        for (int i = tid; i < 2048; i += 256) {
            const int cc = i >> 7, pp = i & 127;
            B_s[cc][pp] = mtB[(c0 + cc) * HW + p0 + pp];
        }
        __syncthreads();
        #pragma unroll
        for (int cc = 0; cc < 16; ++cc) {
            float4 a0 = *(const float4*)&A_s[cc][ty * 8];
            float4 a1 = *(const float4*)&A_s[cc][ty * 8 + 4];
            float4 bv = *(const float4*)&B_s[cc][tx * 4];
            const f32x2 b0 = pack2(bv.x, bv.y), b1 = pack2(bv.z, bv.w);
            const float a[8] = {a0.x, a0.y, a0.z, a0.w, a1.x, a1.y, a1.z, a1.w};
            #pragma unroll
            for (int i = 0; i < 8; ++i) {
                const f32x2 ab = pack2(a[i], a[i]);
                acc2[i][0] = fma2(ab, b0, acc2[i][0]);
                acc2[i][1] = fma2(ab, b1, acc2[i][1]);
            }
        }
        __syncthreads();
    }
    #pragma unroll
    for (int i = 0; i < 8; ++i) {
        const int e = e0 + ty * 8 + i;
        const float sc = bn1g[e] * rsqrtf(bn1v[e] + EPSS);
        const float sh = bn1b[e] - bn1m[e] * sc;
        const float gbv = gbias[e];
        const float2 u10 = unpk(acc1[i][0]), u11 = unpk(acc1[i][1]);
        const float2 u20 = unpk(acc2[i][0]), u21 = unpk(acc2[i][1]);
        const float av1[4] = {u10.x, u10.y, u11.x, u11.y};
        const float av2[4] = {u20.x, u20.y, u21.x, u21.y};
        float res[4];
        #pragma unroll
        for (int j = 0; j < 4; ++j) {
            const float evv = av1[j] * sc + sh;
            const float ev = evv / (1.f + expf(-evv));       // silu
            const float gt = 1.f / (1.f + expf(-(av2[j] + gbv)));
            res[j] = ev * gt;
        }
        *(float4*)&g_eg[(b * Ee + e) * HW + p0 + tx * 4] =
            make_float4(res[0], res[1], res[2], res[3]);
    }
}

// ---------------- K3: scores[t,b,n,p] = qk[t,n,:] . mt[b,:,p] + sb ----------------
__global__ void __launch_bounds__(256) k3_scores() {
    __shared__ float qk_s[16][256];
    __shared__ float sb_s[16];
    const int b = blockIdx.y;
    const int tid = threadIdx.x;
    const int p = blockIdx.x * 256 + tid;
    for (int i = tid; i < 4096; i += 256) qk_s[i >> 8][i & 255] = g_qk[i];
    if (tid < 16) sb_s[tid] = g_sb[tid];
    __syncthreads();
    float acc[16];
    #pragma unroll
    for (int r = 0; r < 16; ++r) acc[r] = sb_s[r];
    const float* mtB = g_mt + b * Qq * HW + p;
    #pragma unroll 4
    for (int c = 0; c < 256; ++c) {
        const float mv = mtB[c * HW];
        #pragma unroll
        for (int r = 0; r < 16; ++r) acc[r] = fmaf(qk_s[r][c], mv, acc[r]);
    }
    #pragma unroll
    for (int r = 0; r < 16; ++r) {
        const int t = r >> 2, n = r & 3;
        g_att[(t * 16 + b * 4 + n) * HW + p] = acc[r];
    }
}

// ---------------- K4: softmax over p (64 rows) ----------------
__global__ void k4_softmax() {
    const int tid = threadIdx.x;
    float* row = g_att + blockIdx.x * HW;
    __shared__ float red[256];
    float mx = -1e30f;
    for (int i = tid; i < HW; i += 256) mx = fmaxf(mx, row[i]);
    red[tid] = mx;
    __syncthreads();
    for (int s = 128; s; s >>= 1) {
        if (tid < s) red[tid] = fmaxf(red[tid], red[tid + s]);
        __syncthreads();
    }
    mx = red[0];
    __syncthreads();
    float sm = 0.f;
    for (int i = tid; i < HW; i += 256) sm += expf(row[i] - mx);
    red[tid] = sm;
    __syncthreads();
    for (int s = 128; s; s >>= 1) {
        if (tid < s) red[tid] += red[tid + s];
        __syncthreads();
    }
    const float inv = 1.f / red[0];
    for (int i = tid; i < HW; i += 256) row[i] = expf(row[i] - mx) * inv;
}

// ---------------- K5: pooled[t,b,n,c] = sum_p attw * mt[b,c,p] ----------------
__global__ void __launch_bounds__(256) k5_pooled() {
    __shared__ float mtT[64][65];
    __shared__ float awT[16][65];
    const int b = blockIdx.z, c0 = blockIdx.y * 64, slab = blockIdx.x * 1024;
    const int tid = threadIdx.x, cl = tid & 63, g = tid >> 6;
    float acc[4] = {};
    for (int pc = 0; pc < 1024; pc += 64) {
        const int pbase = slab + pc;
        for (int i = tid; i < 4096; i += 256) {
            const int cc = i >> 6, pj = i & 63;
            mtT[cc][pj] = g_mt[(b * Qq + c0 + cc) * HW + pbase + pj];
        }
        for (int i = tid; i < 1024; i += 256) {
            const int r = i >> 6, pj = i & 63;
            const int t = r >> 2, n = r & 3;
            awT[r][pj] = g_att[(t * 16 + b * 4 + n) * HW + pbase + pj];
        }
        __syncthreads();
        #pragma unroll 16
        for (int pj = 0; pj < 64; ++pj) {
            const float mv = mtT[cl][pj];
            #pragma unroll
            for (int rr = 0; rr < 4; ++rr)
                acc[rr] = fmaf(awT[g * 4 + rr][pj], mv, acc[rr]);
        }
        __syncthreads();
    }
    #pragma unroll
    for (int rr = 0; rr < 4; ++rr) {
        const int r = g * 4 + rr, t = r >> 2, n = r & 3;
        atomicAdd(&g_pooled[((t * 4 + b) * 4 + n) * Qq + c0 + cl], acc[rr]);
    }
}

// ---------------- K6: attended -> state -> gamma/beta (tiny) ----------------
__global__ void k6_state(const float* __restrict__ ipw, const float* __restrict__ ipb,
                         const float* __restrict__ opw, const float* __restrict__ opb,
                         const float* __restrict__ fw, const float* __restrict__ fb) {
    const int tb = blockIdx.x;  // t*4+b
    __shared__ float pl[1024], att[256], st[256];
    const int tid = threadIdx.x, lane = tid & 31, warp = tid >> 5;
    for (int i = tid; i < 1024; i += 256) pl[i] = g_pooled[tb * 1024 + i];
    __syncthreads();
    for (int o = warp * 32; o < warp * 32 + 32; ++o) {
        const int n = o >> 6;
        float s = 0.f;
        for (int c = lane; c < 256; c += 32) s = fmaf(pl[n * 256 + c], ipw[(512 + o) * 256 + c], s);
        #pragma unroll
        for (int off = 16; off; off >>= 1) s += __shfl_xor_sync(0xffffffffu, s, off);
        if (lane == 0) att[o] = s + ipb[512 + o];
    }
    __syncthreads();
    for (int o = warp * 32; o < warp * 32 + 32; ++o) {
        float s = 0.f;
        for (int c = lane; c < 256; c += 32) s = fmaf(att[c], opw[o * 256 + c], s);
        #pragma unroll
        for (int off = 16; off; off >>= 1) s += __shfl_xor_sync(0xffffffffu, s, off);
        if (lane == 0) st[o] = s + opb[o];
    }
    __syncthreads();
    for (int o = warp * 48; o < warp * 48 + 48; ++o) {
        float s = 0.f;
        for (int c = lane; c < 256; c += 32) s = fmaf(st[c], fw[o * 256 + c], s);
        #pragma unroll
        for (int off = 16; off; off >>= 1) s += __shfl_xor_sync(0xffffffffu, s, off);
        if (lane == 0) {
            s += fb[o];
            if (o < Ee) g_gamma[tb * Ee + o] = s;
            else        g_beta[tb * Ee + o - Ee] = s;
        }
    }
}

// ---------------- K7: 3x3 conv (x built on the fly, FFMA2) + bn2 + silu + mask ----------------
__global__ void __launch_bounds__(256, 2) k7_conv(const float* __restrict__ w,
                                                  const float* __restrict__ bn2g,
                                                  const float* __restrict__ bn2b,
                                                  const float* __restrict__ bn2m,
                                                  const float* __restrict__ bn2v,
                                                  float* __restrict__ out) {
    const int img = blockIdx.z / 6;            // t*4+b
    const int f0 = (blockIdx.z % 6) * 32;
    const int t = img >> 2, b = img & 3;
    const int h0 = blockIdx.y * 16, w0 = blockIdx.x * 32;
    const int tid = threadIdx.x;

    if (!g_mask[b * Stq + t]) {                // active_mask[b][t] == 0 -> zeros
        // 32 filters * 16 rows * 32 cols = 4096 float4
        for (int i = tid; i < 4096; i += 256) {
            const int f = i >> 7, rem = i & 127, r = rem >> 3, c4 = rem & 7;
            *(float4*)&out[((img * Ee + f0 + f) * Hh + h0 + r) * Ww + w0 + c4 * 4] =
                make_float4(0.f, 0.f, 0.f, 0.f);
        }
        return;
    }

    __shared__ float in_s[8][18][36];          // pitch 36 -> 16B-aligned float4 rows
    __shared__ float w_s[72][32];
    const int tf = tid >> 6, tpg = tid & 63;
    const int row = tpg >> 2, col8 = (tpg & 3) << 3;
    f32x2 acc[4][8];                           // filter-pair x pixel
    #pragma unroll
    for (int i = 0; i < 4; ++i)
        #pragma unroll
        for (int j = 0; j < 8; ++j) acc[i][j] = 0ull;

    const float* egB = g_eg + b * Ee * HW;
    const float* gam = g_gamma + img * Ee;
    const float* bet = g_beta + img * Ee;

    for (int e0 = 0; e0 < Ee; e0 += 8) {
        for (int i = tid; i < 2304; i += 256) {
            const int f = i & 31, rest = i >> 5;         // rest = e*9+k
            const int e = rest / 9, k = rest - e * 9;
            w_s[rest][f] = w[((f0 + f) * Ee + e0 + e) * 9 + k];
        }
        for (int i = tid; i < 8 * 18 * 34; i += 256) {
            const int e = i / 612, rem = i - e * 612, rr = rem / 34, cc = rem - rr * 34;
            const int gh = h0 - 1 + rr, gw = w0 - 1 + cc;
            float v = 0.f;
            if (gh >= 0 && gh < Hh && gw >= 0 && gw < Ww) {
                v = egB[(e0 + e) * HW + gh * Ww + gw] * (1.f + gam[e0 + e]) + bet[e0 + e];
            }
            in_s[e][rr][cc] = v;
        }
        __syncthreads();
        for (int e = 0; e < 8; ++e) {
            #pragma unroll
            for (int ky = 0; ky < 3; ++ky) {
                const float* rp = &in_s[e][row + ky][col8];
                const float4 r0 = *(const float4*)rp;
                const float4 r1 = *(const float4*)(rp + 4);
                const float4 r2 = *(const float4*)(rp + 8);
                const float rr[10] = {r0.x, r0.y, r0.z, r0.w,
                                      r1.x, r1.y, r1.z, r1.w,
                                      r2.x, r2.y};
                f32x2 bc[10];
                #pragma unroll
                for (int c = 0; c < 10; ++c) bc[c] = pack2(rr[c], rr[c]);
                #pragma unroll
                for (int kx = 0; kx < 3; ++kx) {
                    const float* wrow = &w_s[(e * 3 + ky) * 3 + kx][tf * 8];
                    const float4 w0v = *(const float4*)wrow;
                    const float4 w1v = *(const float4*)(wrow + 4);
                    const f32x2 wp[4] = {pack2(w0v.x, w0v.y), pack2(w0v.z, w0v.w),
                                         pack2(w1v.x, w1v.y), pack2(w1v.z, w1v.w)};
                    #pragma unroll
                    for (int ip = 0; ip < 4; ++ip)
                        #pragma unroll
                        for (int j = 0; j < 8; ++j)
                            acc[ip][j] = fma2(wp[ip], bc[kx + j], acc[ip][j]);
                }
            }
        }
        __syncthreads();
    }

    #pragma unroll
    for (int i = 0; i < 8; ++i) {
        const int f = f0 + tf * 8 + i;
        const float sc = bn2g[f] * rsqrtf(bn2v[f] + EPSS);
        const float sh = bn2b[f] - bn2m[f] * sc;
        float* orow = out + ((img * Ee + f) * Hh + h0 + row) * Ww + w0 + col8;
        float vals[8];
        #pragma unroll
        for (int j = 0; j < 8; ++j) {
            const float2 u = unpk(acc[i >> 1][j]);
            const float a = (i & 1) ? u.y : u.x;
            const float y = a * sc + sh;
            vals[j] = y / (1.f + expf(-y));   // silu; mask==1 here
        }
        *(float4*)&orow[0] = make_float4(vals[0], vals[1], vals[2], vals[3]);
        *(float4*)&orow[4] = make_float4(vals[4], vals[5], vals[6], vals[7]);
    }
}

// ---------------- launch ----------------
extern "C" void kernel_launch(void* const* d_in, const int* in_sizes, int n_in,
                              void* d_out, int out_size) {
    const float* memory = (const float*)d_in[0];
    const unsigned char* active_mask_raw = (const unsigned char*)d_in[1];
    const float* stem = (const float*)d_in[2];
    const float* mpw  = (const float*)d_in[3];
    const float* ipw  = (const float*)d_in[4];
    const float* ipb  = (const float*)d_in[5];
    const float* opw  = (const float*)d_in[6];
    const float* opb  = (const float*)d_in[7];
    const float* evw  = (const float*)d_in[8];
    const float* bn1g = (const float*)d_in[9];
    const float* bn1b = (const float*)d_in[10];
    const float* bn1m = (const float*)d_in[11];
    const float* bn1v = (const float*)d_in[12];
    const float* gw   = (const float*)d_in[13];
    const float* gbb  = (const float*)d_in[14];
    const float* fw   = (const float*)d_in[15];
    const float* fb   = (const float*)d_in[16];
    const float* outw = (const float*)d_in[17];
    const float* bn2g = (const float*)d_in[18];
    const float* bn2b = (const float*)d_in[19];
    const float* bn2m = (const float*)d_in[20];
    const float* bn2v = (const float*)d_in[21];
    float* out = (float*)d_out;

    k_mask<<<1, 1>>>(active_mask_raw);
    k1_mt<<<dim3(128, 4, 4), 256>>>(memory, mpw);
    k0_qk<<<1, 256>>>(stem, ipw, ipb);
    k2_eg<<<dim3(128, 3, 4), 256>>>(memory, evw, gw, gbb, bn1g, bn1b, bn1m, bn1v);
    k3_scores<<<dim3(64, 4), 256>>>();
    k4_softmax<<<64, 256>>>();
    k5_pooled<<<dim3(16, 4, 4), 256>>>();
    k6_state<<<16, 256>>>(ipw, ipb, opw, opb, fw, fb);
    k7_conv<<<dim3(4, 8, 96), 256>>>(outw, bn2g, bn2b, bn2m, bn2v, out);
}